// round 5
// baseline (speedup 1.0000x reference)
#include <cuda_runtime.h>

#define WFULL 0xFFFFFFFFu

// Per-batch loss scratch (no dynamic allocation allowed).
__device__ float g_loss[4096];

// Affine-recurrence warp scan for the delete chain.
// Elements j=1..64: fD[j] = c_j + d_j * fD[j-1], fD[0] = 0.
// Lane t owns elements j=2t+1 (c1, d=aDD0) and j=2t+2 (c2, d=aDD1).
// The multiplicative scan factors Ds0..Ds4 are constant across l (precomputed).
__device__ __forceinline__ void d_chain_scan(
    float c1, float c2, float aDD0, float aDD1,
    float Ds0, float Ds1, float Ds2, float Ds3, float Ds4,
    int lane, float& D0, float& D1, float& D64)
{
    float C = fmaf(aDD1, c1, c2);   // pair composite offset
    float u;
    u = __shfl_up_sync(WFULL, C, 1);  if (lane >= 1)  C = fmaf(Ds0, u, C);
    u = __shfl_up_sync(WFULL, C, 2);  if (lane >= 2)  C = fmaf(Ds1, u, C);
    u = __shfl_up_sync(WFULL, C, 4);  if (lane >= 4)  C = fmaf(Ds2, u, C);
    u = __shfl_up_sync(WFULL, C, 8);  if (lane >= 8)  C = fmaf(Ds3, u, C);
    u = __shfl_up_sync(WFULL, C, 16); if (lane >= 16) C = fmaf(Ds4, u, C);
    float Cex = __shfl_up_sync(WFULL, C, 1);  // exclusive prefix = fD[2t]
    if (lane == 0) Cex = 0.f;
    D0  = Cex;                    // fD[2t]
    D1  = fmaf(aDD0, Cex, c1);    // fD[2t+1]
    D64 = C;                      // lane 31: fD[64]
}

__global__ __launch_bounds__(256, 4)
void phmm_fwd_kernel(const int*   __restrict__ x,
                     const float* __restrict__ tp,   // (B,65,7)
                     const float* __restrict__ ep,   // (B,64,4)
                     const float* __restrict__ mus,  // (B,16)
                     const float* __restrict__ lvs,  // (B,16)
                     int B)
{
    const int b = (int)((blockIdx.x * blockDim.x + threadIdx.x) >> 5);
    if (b >= B) return;                 // warp-uniform exit
    const int lane = threadIdx.x & 31;
    const int k0 = lane * 2;            // states k0, k0+1; lane31 also owns k=64

    // ---- transitions (exp once) ----
    // order: M2M, M2I, M2D, I2M, I2I, D2M, D2D
    const float* a = tp + ((size_t)b * 65 + k0) * 7;
    const float aMM0 = __expf(a[0]),  aMI0 = __expf(a[1]),  aMD0 = __expf(a[2]);
    const float aIM0 = __expf(a[3]),  aII0 = __expf(a[4]),  aDM0 = __expf(a[5]);
    const float aDD0 = __expf(a[6]);
    const float aMM1 = __expf(a[7]),  aMI1 = __expf(a[8]),  aMD1 = __expf(a[9]);
    const float aIM1 = __expf(a[10]), aII1 = __expf(a[11]), aDM1 = __expf(a[12]);
    const float aDD1 = __expf(a[13]);

    float aMM64 = 0.f, aMI64 = 0.f, aIM64 = 0.f, aII64 = 0.f, aDM64 = 0.f;
    if (lane == 31) {
        const float* a64 = tp + ((size_t)b * 65 + 64) * 7;
        aMM64 = __expf(a64[0]); aMI64 = __expf(a64[1]);
        aIM64 = __expf(a64[3]); aII64 = __expf(a64[4]); aDM64 = __expf(a64[5]);
    }

    // ---- emissions (exp once) ----
    const float4* e4 = (const float4*)(ep + ((size_t)b * 64 + k0) * 4);
    const float4 er0 = e4[0], er1 = e4[1];
    const float e00 = __expf(er0.x), e01 = __expf(er0.y), e02 = __expf(er0.z), e03 = __expf(er0.w);
    const float e10 = __expf(er1.x), e11 = __expf(er1.y), e12 = __expf(er1.z), e13 = __expf(er1.w);

    // ---- symbol stream: 4 symbols per lane, byte-packed ----
    const int4 xv = *(const int4*)(x + (size_t)b * 128 + lane * 4);
    const unsigned xpk = (unsigned)xv.x | ((unsigned)xv.y << 8)
                       | ((unsigned)xv.z << 16) | ((unsigned)xv.w << 24);

    // ---- constant multiplicative scan factors for the D chain ----
    float Ds0, Ds1, Ds2, Ds3, Ds4;
    {
        float Dc = aDD0 * aDD1;   // pair product (segment of 1 thread)
        Ds0 = Dc; { float u = __shfl_up_sync(WFULL, Dc, 1); if (lane >= 1) Dc *= u; }
        Ds1 = Dc; { float u = __shfl_up_sync(WFULL, Dc, 2); if (lane >= 2) Dc *= u; }
        Ds2 = Dc; { float u = __shfl_up_sync(WFULL, Dc, 4); if (lane >= 4) Dc *= u; }
        Ds3 = Dc; { float u = __shfl_up_sync(WFULL, Dc, 8); if (lane >= 8) Dc *= u; }
        Ds4 = Dc;
    }

    // ---- initial state: fM[0]=1, everything else ~0 (exp(-100) ≈ 0) ----
    float M0 = (lane == 0) ? 1.0f : 0.0f, M1 = 0.0f;
    float I0 = 0.0f, I1 = 0.0f;
    float M64 = 0.0f, I64 = 0.0f, D64 = 0.0f;
    float D0, D1;
    d_chain_scan(aMD0 * M0, aMD1 * M1, aDD0, aDD1,
                 Ds0, Ds1, Ds2, Ds3, Ds4, lane, D0, D1, D64);

    int ez = 0;   // exact integer accumulator of rescale exponents

    for (int l = 0; l < 128; ++l) {
        const unsigned word = __shfl_sync(WFULL, xpk, l >> 2);
        const int sym = (int)((word >> ((l & 3) * 8)) & 3u);
        const float es0 = (sym & 1) ? ((sym & 2) ? e03 : e01) : ((sym & 2) ? e02 : e00);
        const float es1 = (sym & 1) ? ((sym & 2) ? e13 : e11) : ((sym & 2) ? e12 : e10);

        // match updates (produce newM[2t+1], newM[2t+2] from states 2t, 2t+1)
        const float m_out0 = es0 * fmaf(aMM0, M0, fmaf(aIM0, I0, aDM0 * D0));
        const float m_out1 = es1 * fmaf(aMM1, M1, fmaf(aIM1, I1, aDM1 * D1));

        // insert updates (use OLD fM, fI)
        float nI0 = 0.25f * fmaf(aMI0, M0, aII0 * I0);
        float nI1 = 0.25f * fmaf(aMI1, M1, aII1 * I1);
        float nI64 = 0.f, nM64 = 0.f;
        if (lane == 31) {
            nI64 = 0.25f * fmaf(aMI64, M64, aII64 * I64);
            nM64 = m_out1;                 // newM[64]
        }

        // shift: newM[2t] comes from lane t-1's second product
        float nM1 = m_out0;
        float nM0 = __shfl_up_sync(WFULL, m_out1, 1);
        if (lane == 0) nM0 = 0.f;          // newM[0] = exp(NEG) ~ 0

        // power-of-2 rescale by block max (exact; no MUFU)
        float mx = fmaxf(fmaxf(nM0, nM1), fmaxf(nI0, nI1));
        if (lane == 31) mx = fmaxf(mx, fmaxf(nM64, nI64));
        mx = fmaxf(mx, __shfl_xor_sync(WFULL, mx, 16));
        mx = fmaxf(mx, __shfl_xor_sync(WFULL, mx, 8));
        mx = fmaxf(mx, __shfl_xor_sync(WFULL, mx, 4));
        mx = fmaxf(mx, __shfl_xor_sync(WFULL, mx, 2));
        mx = fmaxf(mx, __shfl_xor_sync(WFULL, mx, 1));
        const int eb = (__float_as_int(mx) >> 23) - 127;       // floor(log2 mx)
        const float scale = __int_as_float((127 - eb) << 23);  // exact 2^(-eb)
        ez += eb;

        M0 = nM0 * scale; M1 = nM1 * scale;
        I0 = nI0 * scale; I1 = nI1 * scale;
        M64 = nM64 * scale; I64 = nI64 * scale;

        // delete chain from NEW (scaled) fM
        d_chain_scan(aMD0 * M0, aMD1 * M1, aDD0, aDD1,
                     Ds0, Ds1, Ds2, Ds3, Ds4, lane, D0, D1, D64);
    }

    // ---- KLD (lanes 0..15), reduced across warp ----
    float kt = 0.f;
    if (lane < 16) {
        const float mu = mus[(size_t)b * 16 + lane];
        const float lv = lvs[(size_t)b * 16 + lane];
        kt = 1.0f + lv - mu * mu - __expf(lv);
    }
    kt += __shfl_xor_sync(WFULL, kt, 16);
    kt += __shfl_xor_sync(WFULL, kt, 8);
    kt += __shfl_xor_sync(WFULL, kt, 4);
    kt += __shfl_xor_sync(WFULL, kt, 2);
    kt += __shfl_xor_sync(WFULL, kt, 1);
    const float kld = -0.5f * kt;

    if (lane == 31) {
        float fin = fmaf(aMM64, M64, fmaf(aIM64, I64, aDM64 * D64));
        fin = fmaxf(fin, 1.4e-45f);   // guard against log(0)
        const float recon = -(__logf(fin) + 0.69314718055994530942f * (float)ez);
        g_loss[b] = recon + kld;
    }
}

// Deterministic fixed-order reduction of per-batch losses.
__global__ void phmm_reduce_kernel(float* __restrict__ out, int B)
{
    __shared__ double s[256];
    double acc = 0.0;
    for (int i = threadIdx.x; i < B; i += 256) acc += (double)g_loss[i];
    s[threadIdx.x] = acc;
    __syncthreads();
    for (int w = 128; w > 0; w >>= 1) {
        if (threadIdx.x < w) s[threadIdx.x] += s[threadIdx.x + w];
        __syncthreads();
    }
    if (threadIdx.x == 0) out[0] = (float)(s[0] / (double)B);
}

extern "C" void kernel_launch(void* const* d_in, const int* in_sizes, int n_in,
                              void* d_out, int out_size)
{
    const int*   x   = (const int*)d_in[0];
    const float* tp  = (const float*)d_in[1];
    const float* ep  = (const float*)d_in[2];
    const float* mus = (const float*)d_in[3];
    const float* lvs = (const float*)d_in[4];
    float* out = (float*)d_out;

    int B = in_sizes[0] / 128;
    if (B > 4096) B = 4096;
    const int warpsPerBlock = 8;
    const int blocks = (B + warpsPerBlock - 1) / warpsPerBlock;

    phmm_fwd_kernel<<<blocks, 256>>>(x, tp, ep, mus, lvs, B);
    phmm_reduce_kernel<<<1, 256>>>(out, B);
}

// round 7
// speedup vs baseline: 1.7766x; 1.7766x over previous
#include <cuda_runtime.h>

#define WFULL 0xFFFFFFFFu

// Deterministic fixed-point accumulator (integer adds are associative).
__device__ unsigned long long g_acc = 0ULL;
__device__ unsigned int g_ticket = 0u;

// Affine-recurrence warp scan for the delete chain.
// fD[j] = c_j + d_j * fD[j-1], fD[0]=0. Lane t owns j=2t+1 (c1,aDD0), j=2t+2 (c2,aDD1).
// Multiplicative scan factors Ds0..Ds4 are constant across l (precomputed).
__device__ __forceinline__ void d_chain_scan(
    float c1, float c2, float aDD0, float aDD1,
    float Ds0, float Ds1, float Ds2, float Ds3, float Ds4,
    int lane, float& D0, float& D1, float& D64)
{
    float C = fmaf(aDD1, c1, c2);   // pair composite offset
    float u;
    u = __shfl_up_sync(WFULL, C, 1);  if (lane >= 1)  C = fmaf(Ds0, u, C);
    u = __shfl_up_sync(WFULL, C, 2);  if (lane >= 2)  C = fmaf(Ds1, u, C);
    u = __shfl_up_sync(WFULL, C, 4);  if (lane >= 4)  C = fmaf(Ds2, u, C);
    u = __shfl_up_sync(WFULL, C, 8);  if (lane >= 8)  C = fmaf(Ds3, u, C);
    u = __shfl_up_sync(WFULL, C, 16); if (lane >= 16) C = fmaf(Ds4, u, C);
    float Cex = __shfl_up_sync(WFULL, C, 1);  // exclusive prefix = fD[2t]
    if (lane == 0) Cex = 0.f;
    D0  = Cex;                    // fD[2t]
    D1  = fmaf(aDD0, Cex, c1);    // fD[2t+1]
    D64 = C;                      // lane 31: fD[64]
}

__global__ __launch_bounds__(64, 16)
void phmm_fused_kernel(const int*   __restrict__ x,
                       const float* __restrict__ tp,   // (B,65,7)
                       const float* __restrict__ ep,   // (B,64,4)
                       const float* __restrict__ mus,  // (B,16)
                       const float* __restrict__ lvs,  // (B,16)
                       float* __restrict__ out, int B)
{
    __shared__ float2 es_sm[2][4][32];   // [warp][sym][pair-lane]
    __shared__ long long s_part[2];

    const int w    = threadIdx.x >> 5;
    const int lane = threadIdx.x & 31;
    const int b    = blockIdx.x * 2 + w;
    long long my = 0;

    if (b < B) {
        const int k0 = lane * 2;   // states k0, k0+1; lane31 additionally tracks k=64

        // ---- transitions (exp once): M2M,M2I,M2D,I2M,I2I,D2M,D2D ----
        const float* a = tp + ((size_t)b * 65 + k0) * 7;
        const float aMM0 = __expf(a[0]),  aMI0 = __expf(a[1]),  aMD0 = __expf(a[2]);
        const float aIM0 = __expf(a[3]),  aII0 = __expf(a[4]),  aDM0 = __expf(a[5]);
        const float aDD0 = __expf(a[6]);
        const float aMM1 = __expf(a[7]),  aMI1 = __expf(a[8]),  aMD1 = __expf(a[9]);
        const float aIM1 = __expf(a[10]), aII1 = __expf(a[11]), aDM1 = __expf(a[12]);
        const float aDD1 = __expf(a[13]);

        float aMI64 = 0.f, aII64 = 0.f;   // zero on lanes != 31 -> their I64 stays 0
        if (lane == 31) {
            const float* a64 = tp + ((size_t)b * 65 + 64) * 7;
            aMI64 = __expf(a64[1]); aII64 = __expf(a64[4]);
        }

        // ---- emissions -> per-thread SMEM lookup table (written/read by same thread) ----
        const float4* e4 = (const float4*)(ep + ((size_t)b * 64 + k0) * 4);
        const float4 er0 = e4[0], er1 = e4[1];
        es_sm[w][0][lane] = make_float2(__expf(er0.x), __expf(er1.x));
        es_sm[w][1][lane] = make_float2(__expf(er0.y), __expf(er1.y));
        es_sm[w][2][lane] = make_float2(__expf(er0.z), __expf(er1.z));
        es_sm[w][3][lane] = make_float2(__expf(er0.w), __expf(er1.w));

        // ---- symbol stream: 4 symbols per lane, byte-packed ----
        const int4 xv = *(const int4*)(x + (size_t)b * 128 + lane * 4);
        const unsigned xpk = (unsigned)xv.x | ((unsigned)xv.y << 8)
                           | ((unsigned)xv.z << 16) | ((unsigned)xv.w << 24);

        // ---- constant multiplicative scan factors for the D chain ----
        float Ds0, Ds1, Ds2, Ds3, Ds4;
        {
            float Dc = aDD0 * aDD1;
            Ds0 = Dc; { float u2 = __shfl_up_sync(WFULL, Dc, 1); if (lane >= 1) Dc *= u2; }
            Ds1 = Dc; { float u2 = __shfl_up_sync(WFULL, Dc, 2); if (lane >= 2) Dc *= u2; }
            Ds2 = Dc; { float u2 = __shfl_up_sync(WFULL, Dc, 4); if (lane >= 4) Dc *= u2; }
            Ds3 = Dc; { float u2 = __shfl_up_sync(WFULL, Dc, 8); if (lane >= 8) Dc *= u2; }
            Ds4 = Dc;
        }

        // ---- initial state: fM[0]=1, everything else ~0 (exp(-100) ~ 0) ----
        float M0 = (lane == 0) ? 1.0f : 0.0f, M1 = 0.0f;
        float I0 = 0.0f, I1 = 0.0f, M64 = 0.0f, I64 = 0.0f;
        float D0, D1, D64;
        d_chain_scan(aMD0 * M0, aMD1 * M1, aDD0, aDD1,
                     Ds0, Ds1, Ds2, Ds3, Ds4, lane, D0, D1, D64);

        int ez = 0;   // exact integer accumulator of rescale exponents

        #pragma unroll 1
        for (int g = 0; g < 32; ++g) {
            // one symbol word per group of 4 steps; issue all 4 emission loads early
            const unsigned word = __shfl_sync(WFULL, xpk, g);
            const float2 esA = es_sm[w][word & 3u][lane];
            const float2 esB = es_sm[w][(word >> 8) & 3u][lane];
            const float2 esC = es_sm[w][(word >> 16) & 3u][lane];
            const float2 esD = es_sm[w][(word >> 24) & 3u][lane];

            #pragma unroll
            for (int j = 0; j < 4; ++j) {
                const float2 es = (j == 0) ? esA : (j == 1) ? esB : (j == 2) ? esC : esD;
                const float m_out0 = es.x * fmaf(aMM0, M0, fmaf(aIM0, I0, aDM0 * D0));
                const float m_out1 = es.y * fmaf(aMM1, M1, fmaf(aIM1, I1, aDM1 * D1));
                const float nI64 = 0.25f * fmaf(aMI64, M64, aII64 * I64);  // uses OLD M64
                I0 = 0.25f * fmaf(aMI0, M0, aII0 * I0);
                I1 = 0.25f * fmaf(aMI1, M1, aII1 * I1);
                M64 = m_out1;         // meaningful on lane31 only; harmless elsewhere
                I64 = nI64;
                M1 = m_out0;
                M0 = __shfl_up_sync(WFULL, m_out1, 1);
                if (lane == 0) M0 = 0.f;   // fM_new[0] = exp(NEG) ~ 0
                d_chain_scan(aMD0 * M0, aMD1 * M1, aDD0, aDD1,
                             Ds0, Ds1, Ds2, Ds3, Ds4, lane, D0, D1, D64);
            }

            // power-of-2 rescale once per 4 steps (exact; D scales linearly with M)
            float mx = fmaxf(fmaxf(M0, M1), fmaxf(I0, I1));
            if (lane == 31) mx = fmaxf(mx, fmaxf(M64, I64));
            mx = fmaxf(mx, __shfl_xor_sync(WFULL, mx, 16));
            mx = fmaxf(mx, __shfl_xor_sync(WFULL, mx, 8));
            mx = fmaxf(mx, __shfl_xor_sync(WFULL, mx, 4));
            mx = fmaxf(mx, __shfl_xor_sync(WFULL, mx, 2));
            mx = fmaxf(mx, __shfl_xor_sync(WFULL, mx, 1));
            const int eb = (__float_as_int(mx) >> 23) - 127;       // floor(log2 mx)
            const float scale = __int_as_float((127 - eb) << 23);  // exact 2^(-eb)
            ez += eb;
            M0 *= scale; M1 *= scale; I0 *= scale; I1 *= scale;
            M64 *= scale; I64 *= scale;
            D0 *= scale; D1 *= scale; D64 *= scale;
        }

        // ---- KLD (lanes 0..15), reduced across warp ----
        float kt = 0.f;
        if (lane < 16) {
            const float mu = mus[(size_t)b * 16 + lane];
            const float lv = lvs[(size_t)b * 16 + lane];
            kt = 1.0f + lv - mu * mu - __expf(lv);
        }
        kt += __shfl_xor_sync(WFULL, kt, 16);
        kt += __shfl_xor_sync(WFULL, kt, 8);
        kt += __shfl_xor_sync(WFULL, kt, 4);
        kt += __shfl_xor_sync(WFULL, kt, 2);
        kt += __shfl_xor_sync(WFULL, kt, 1);

        if (lane == 31) {
            const float* a64 = tp + ((size_t)b * 65 + 64) * 7;
            const float aMM64 = __expf(a64[0]);
            const float aIM64 = __expf(a64[3]);
            const float aDM64 = __expf(a64[5]);
            float fin = fmaf(aMM64, M64, fmaf(aIM64, I64, aDM64 * D64));
            fin = fmaxf(fin, 1.4e-45f);
            const float recon = -(__logf(fin) + 0.69314718055994530942f * (float)ez);
            const float loss = recon - 0.5f * kt;
            my = llrintf(loss * 67108864.0f);   // fixed point, 2^26
        }
    }

    // ---- deterministic block + grid reduction ----
    if (lane == 31) s_part[w] = my;
    __syncthreads();
    if (threadIdx.x == 0) {
        const unsigned long long tot = (unsigned long long)(s_part[0] + s_part[1]);
        atomicAdd(&g_acc, tot);
        __threadfence();
        const unsigned int t = atomicAdd(&g_ticket, 1u);
        if (t == gridDim.x - 1) {
            const long long sum = (long long)atomicAdd(&g_acc, 0ULL);
            out[0] = (float)((double)sum / (67108864.0 * (double)B));
            g_acc = 0ULL;     // reset for next graph replay
            g_ticket = 0u;
        }
    }
}

extern "C" void kernel_launch(void* const* d_in, const int* in_sizes, int n_in,
                              void* d_out, int out_size)
{
    const int*   x   = (const int*)d_in[0];
    const float* tp  = (const float*)d_in[1];
    const float* ep  = (const float*)d_in[2];
    const float* mus = (const float*)d_in[3];
    const float* lvs = (const float*)d_in[4];
    float* out = (float*)d_out;

    int B = in_sizes[0] / 128;
    if (B > 4096) B = 4096;
    const int blocks = (B + 1) / 2;   // 2 warps (2 batch elements) per block

    phmm_fused_kernel<<<blocks, 64>>>(x, tp, ep, mus, lvs, out, B);
}

// round 9
// speedup vs baseline: 2.0868x; 1.1746x over previous
#include <cuda_runtime.h>

#define WFULL 0xFFFFFFFFu

// Deterministic fixed-point accumulator (integer adds are associative).
__device__ unsigned long long g_acc = 0ULL;
__device__ unsigned int g_ticket = 0u;

// Delete-chain affine scan, 4 states/lane, 16-lane segments (2 elements/warp).
// fD[k] = aMD[k-1]*fM[k-1] + aDD[k-1]*fD[k-1], fD[0]=0.
// Lane hl owns fD[k0..k0+3] (k0=4*hl); inclusive C at hl = fD[k0+4] (hl=15 -> fD[64]).
__device__ __forceinline__ void d_scan4(
    const float aMD[4], const float d[4], const float Ds[4],
    const float M[4], int hl, float D[4], float& D64)
{
    const float c0 = aMD[0] * M[0], c1 = aMD[1] * M[1];
    const float c2 = aMD[2] * M[2], c3 = aMD[3] * M[3];
    // within-lane composite offset: fD[k0+4] = C + (d0 d1 d2 d3) * fD[k0]
    float t = fmaf(d[1], c0, c1);
    t = fmaf(d[2], t, c2);
    float C = fmaf(d[3], t, c3);
    float u;
    u = __shfl_up_sync(WFULL, C, 1, 16); if (hl >= 1) C = fmaf(Ds[0], u, C);
    u = __shfl_up_sync(WFULL, C, 2, 16); if (hl >= 2) C = fmaf(Ds[1], u, C);
    u = __shfl_up_sync(WFULL, C, 4, 16); if (hl >= 4) C = fmaf(Ds[2], u, C);
    u = __shfl_up_sync(WFULL, C, 8, 16); if (hl >= 8) C = fmaf(Ds[3], u, C);
    float P = __shfl_up_sync(WFULL, C, 1, 16);   // exclusive prefix = fD[k0]
    if (hl == 0) P = 0.f;
    D[0] = P;
    D[1] = fmaf(d[0], P,    c0);
    D[2] = fmaf(d[1], D[1], c1);
    D[3] = fmaf(d[2], D[2], c2);
    D64  = C;                                    // meaningful on hl==15
}

__global__ __launch_bounds__(64, 8)
void phmm_fused4_kernel(const int*   __restrict__ x,
                        const float* __restrict__ tp,   // (B,65,7)
                        const float* __restrict__ ep,   // (B,64,4)
                        const float* __restrict__ mus,  // (B,16)
                        const float* __restrict__ lvs,  // (B,16)
                        float* __restrict__ out, int B)
{
    __shared__ float4 es_sm[2][4][32];   // [warp][sym][lane] -> es for this lane's 4 states
    __shared__ long long s_part[2];

    const int w    = threadIdx.x >> 5;
    const int lane = threadIdx.x & 31;
    const int hl   = lane & 15;          // lane within half-warp segment
    const int e    = lane >> 4;          // which element of the pair
    int b = blockIdx.x * 4 + w * 2 + e;
    const bool valid = (b < B);
    if (!valid) b = B - 1;               // clamp for safe loads

    const int k0 = hl * 4;               // this lane's 4 match states

    // ---- transitions (exp once): order M2M,M2I,M2D,I2M,I2I,D2M,D2D ----
    const float* a = tp + ((size_t)b * 65 + k0) * 7;
    float aMM[4], aMIq[4], aMD[4], aIM[4], aIIq[4], aDM[4], d[4];
    #pragma unroll
    for (int j = 0; j < 4; ++j) {
        aMM[j]  = __expf(a[7 * j + 0]);
        aMIq[j] = 0.25f * __expf(a[7 * j + 1]);   // fold LOG_Q=log(1/4)
        aMD[j]  = __expf(a[7 * j + 2]);
        aIM[j]  = __expf(a[7 * j + 3]);
        aIIq[j] = 0.25f * __expf(a[7 * j + 4]);
        aDM[j]  = __expf(a[7 * j + 5]);
        d[j]    = __expf(a[7 * j + 6]);
    }
    float aMI64q = 0.f, aII64q = 0.f;    // zero on hl!=15 -> I64 stays 0 there
    if (hl == 15) {
        const float* a64 = tp + ((size_t)b * 65 + 64) * 7;
        aMI64q = 0.25f * __expf(a64[1]);
        aII64q = 0.25f * __expf(a64[4]);
    }

    // ---- emissions -> per-thread SMEM table (written & read by same thread) ----
    {
        const float4* e4 = (const float4*)(ep + ((size_t)b * 64 + k0) * 4);
        const float4 f0 = e4[0], f1 = e4[1], f2 = e4[2], f3 = e4[3];
        es_sm[w][0][lane] = make_float4(__expf(f0.x), __expf(f1.x), __expf(f2.x), __expf(f3.x));
        es_sm[w][1][lane] = make_float4(__expf(f0.y), __expf(f1.y), __expf(f2.y), __expf(f3.y));
        es_sm[w][2][lane] = make_float4(__expf(f0.z), __expf(f1.z), __expf(f2.z), __expf(f3.z));
        es_sm[w][3][lane] = make_float4(__expf(f0.w), __expf(f1.w), __expf(f2.w), __expf(f3.w));
    }

    // ---- symbol stream: 8 symbols per lane, 2-bit packed ----
    unsigned xpk;
    {
        const int4* x4 = (const int4*)(x + (size_t)b * 128);
        const int4 xa = x4[2 * hl], xb = x4[2 * hl + 1];
        xpk = (unsigned)xa.x | ((unsigned)xa.y << 2) | ((unsigned)xa.z << 4) | ((unsigned)xa.w << 6)
            | ((unsigned)xb.x << 8) | ((unsigned)xb.y << 10) | ((unsigned)xb.z << 12) | ((unsigned)xb.w << 14);
    }

    // ---- constant multiplicative scan factors ----
    float Ds[4];
    {
        float Dc = d[0] * d[1] * d[2] * d[3];
        float u;
        Ds[0] = Dc; u = __shfl_up_sync(WFULL, Dc, 1, 16); if (hl >= 1) Dc *= u;
        Ds[1] = Dc; u = __shfl_up_sync(WFULL, Dc, 2, 16); if (hl >= 2) Dc *= u;
        Ds[2] = Dc; u = __shfl_up_sync(WFULL, Dc, 4, 16); if (hl >= 4) Dc *= u;
        Ds[3] = Dc;
    }

    // ---- initial state: fM[0]=1, rest ~0 (exp(-100) ~ 0) ----
    float M[4] = {(hl == 0) ? 1.0f : 0.0f, 0.f, 0.f, 0.f};
    float I[4] = {0.f, 0.f, 0.f, 0.f};
    float D[4], M64 = 0.f, I64 = 0.f, D64 = 0.f;
    d_scan4(aMD, d, Ds, M, hl, D, D64);

    int ez = 0;   // exact integer accumulator of rescale exponents

    #pragma unroll 1
    for (int g = 0; g < 32; ++g) {
        const unsigned word = __shfl_sync(WFULL, xpk, g >> 1, 16);
        const unsigned bits = word >> ((g & 1) * 8);   // 4 syms x 2 bits
        const float4 esA = es_sm[w][bits & 3u][lane];
        const float4 esB = es_sm[w][(bits >> 2) & 3u][lane];
        const float4 esC = es_sm[w][(bits >> 4) & 3u][lane];
        const float4 esD = es_sm[w][(bits >> 6) & 3u][lane];

        #pragma unroll
        for (int j = 0; j < 4; ++j) {
            const float4 es = (j == 0) ? esA : (j == 1) ? esB : (j == 2) ? esC : esD;
            const float m0 = es.x * fmaf(aMM[0], M[0], fmaf(aIM[0], I[0], aDM[0] * D[0]));
            const float m1 = es.y * fmaf(aMM[1], M[1], fmaf(aIM[1], I[1], aDM[1] * D[1]));
            const float m2 = es.z * fmaf(aMM[2], M[2], fmaf(aIM[2], I[2], aDM[2] * D[2]));
            const float m3 = es.w * fmaf(aMM[3], M[3], fmaf(aIM[3], I[3], aDM[3] * D[3]));
            const float nI64 = fmaf(aMI64q, M64, aII64q * I64);    // OLD M64
            I[0] = fmaf(aMIq[0], M[0], aIIq[0] * I[0]);
            I[1] = fmaf(aMIq[1], M[1], aIIq[1] * I[1]);
            I[2] = fmaf(aMIq[2], M[2], aIIq[2] * I[2]);
            I[3] = fmaf(aMIq[3], M[3], aIIq[3] * I[3]);
            M64 = m3;            // fM[64] on hl==15; harmless elsewhere
            I64 = nI64;
            const float sh = __shfl_up_sync(WFULL, m3, 1, 16);
            M[0] = (hl == 0) ? 0.f : sh;   // fM_new[0] = exp(NEG) ~ 0
            M[1] = m0; M[2] = m1; M[3] = m2;
            d_scan4(aMD, d, Ds, M, hl, D, D64);
        }

        // power-of-2 rescale once per 4 steps (exact; no MUFU)
        float mx = fmaxf(fmaxf(fmaxf(M[0], M[1]), fmaxf(M[2], M[3])),
                         fmaxf(fmaxf(I[0], I[1]), fmaxf(I[2], I[3])));
        mx = fmaxf(mx, fmaxf(M64, I64));
        mx = fmaxf(mx, __shfl_xor_sync(WFULL, mx, 8, 16));
        mx = fmaxf(mx, __shfl_xor_sync(WFULL, mx, 4, 16));
        mx = fmaxf(mx, __shfl_xor_sync(WFULL, mx, 2, 16));
        mx = fmaxf(mx, __shfl_xor_sync(WFULL, mx, 1, 16));
        const int eb = (__float_as_int(mx) >> 23) - 127;       // floor(log2 mx)
        const float scale = __int_as_float((127 - eb) << 23);  // exact 2^(-eb)
        ez += eb;
        M[0] *= scale; M[1] *= scale; M[2] *= scale; M[3] *= scale;
        I[0] *= scale; I[1] *= scale; I[2] *= scale; I[3] *= scale;
        D[0] *= scale; D[1] *= scale; D[2] *= scale; D[3] *= scale;
        M64 *= scale; I64 *= scale; D64 *= scale;
    }

    // ---- KLD: one dim per lane of the half, width-16 reduce ----
    float kt;
    {
        const float mu = mus[(size_t)b * 16 + hl];
        const float lv = lvs[(size_t)b * 16 + hl];
        kt = 1.0f + lv - mu * mu - __expf(lv);
        kt += __shfl_xor_sync(WFULL, kt, 8, 16);
        kt += __shfl_xor_sync(WFULL, kt, 4, 16);
        kt += __shfl_xor_sync(WFULL, kt, 2, 16);
        kt += __shfl_xor_sync(WFULL, kt, 1, 16);
    }

    long long my = 0;
    if (hl == 15) {
        const float* a64 = tp + ((size_t)b * 65 + 64) * 7;
        const float aMM64 = __expf(a64[0]);
        const float aIM64 = __expf(a64[3]);
        const float aDM64 = __expf(a64[5]);
        float fin = fmaf(aMM64, M64, fmaf(aIM64, I64, aDM64 * D64));
        fin = fmaxf(fin, 1.4e-45f);
        const float recon = -(__logf(fin) + 0.69314718055994530942f * (float)ez);
        const float loss = recon - 0.5f * kt;
        my = valid ? llrintf(loss * 67108864.0f) : 0LL;   // fixed point, 2^26
    }

    // ---- deterministic block + grid reduction ----
    const long long v15 = __shfl_sync(WFULL, my, 15);
    const long long v31 = __shfl_sync(WFULL, my, 31);
    if (lane == 0) s_part[w] = v15 + v31;
    __syncthreads();
    if (threadIdx.x == 0) {
        const unsigned long long tot = (unsigned long long)(s_part[0] + s_part[1]);
        atomicAdd(&g_acc, tot);
        __threadfence();
        const unsigned int t = atomicAdd(&g_ticket, 1u);
        if (t == gridDim.x - 1) {
            const long long sum = (long long)atomicAdd(&g_acc, 0ULL);
            out[0] = (float)((double)sum / (67108864.0 * (double)B));
            g_acc = 0ULL;     // reset for next graph replay
            g_ticket = 0u;
        }
    }
}

extern "C" void kernel_launch(void* const* d_in, const int* in_sizes, int n_in,
                              void* d_out, int out_size)
{
    const int*   x   = (const int*)d_in[0];
    const float* tp  = (const float*)d_in[1];
    const float* ep  = (const float*)d_in[2];
    const float* mus = (const float*)d_in[3];
    const float* lvs = (const float*)d_in[4];
    float* out = (float*)d_out;

    int B = in_sizes[0] / 128;
    if (B > 4096) B = 4096;
    const int blocks = (B + 3) / 4;   // 4 batch elements per 64-thread block

    phmm_fused4_kernel<<<blocks, 64>>>(x, tp, ep, mus, lvs, out, B);
}